// round 14
// baseline (speedup 1.0000x reference)
#include <cuda_runtime.h>
#include <cuda_fp16.h>
#include <math.h>

// Problem constants (fixed by the dataset)
#define NN 100000
#define EE 3200000
#define KK 1024
#define SLOTS 96           // max degree capacity (deg ~ Binom(3.2M,1e-5); deg>=96 is ~11 sigma)

// ---------------- scratch (device globals; no allocation allowed) -----------
__device__ __align__(16) float  g_x16[NN * 16];  // x padded to 64B rows (float, exact)
__device__ __align__(16) __half g_yh[NN * 16];   // dis[i]*x in fp16, 32B rows (12 used + 4 pad)
__device__ int   g_cnt1[NN];           // degree counter / CSR slot allocator
__device__ float g_dis[NN];
__device__ float g_hd[NN];             // dis[i] * (x_input[i] @ W2)
__device__ float g_agg2[NN];           // layer-2 sums (written at ready rows by k_edge2)
__device__ float g_vd[2];              // global sums of h1.Wv and h1.Wd
__device__ int   g_bucket[SLOTS * NN]; // TRANSPOSED CSR: bucket[slot*NN + node] = dst

// ---------------- kernels ---------------------------------------------------

// (1) zero degree counters + pad x into 64B float rows; zero readout accumulators
__global__ void k_init(const float* __restrict__ x, int n) {
    int i = blockIdx.x * blockDim.x + threadIdx.x;
    if (i < n) {
        g_cnt1[i] = 0;
        const float* p = x + i * 11;
        float4* o = (float4*)&g_x16[i * 16];
        o[0] = make_float4(p[0], p[1], p[2], p[3]);
        o[1] = make_float4(p[4], p[5], p[6], p[7]);
        o[2] = make_float4(p[8], p[9], p[10], 0.f);
    }
    if (i < 2) g_vd[i] = 0.f;
}

// (2) degree count + transposed CSR fill. 8 edges/thread; all 8 atomics issued
//     before any store so 8 ATOMG returns are in flight per thread (scatter is
//     latency-bound: r6 profile had issue=4.1%, L2=52% -- neither saturated).
__global__ void k_scatter(const int* __restrict__ src, const int* __restrict__ dst, int e) {
    int j8 = blockIdx.x * blockDim.x + threadIdx.x;
    int e8 = e >> 3;
    if (j8 < e8) {
        int4 sa = ((const int4*)src)[j8 * 2];
        int4 sb = ((const int4*)src)[j8 * 2 + 1];
        int4 da = ((const int4*)dst)[j8 * 2];
        int4 db = ((const int4*)dst)[j8 * 2 + 1];
        int t0 = atomicAdd(&g_cnt1[sa.x], 1);
        int t1 = atomicAdd(&g_cnt1[sa.y], 1);
        int t2 = atomicAdd(&g_cnt1[sa.z], 1);
        int t3 = atomicAdd(&g_cnt1[sa.w], 1);
        int t4 = atomicAdd(&g_cnt1[sb.x], 1);
        int t5 = atomicAdd(&g_cnt1[sb.y], 1);
        int t6 = atomicAdd(&g_cnt1[sb.z], 1);
        int t7 = atomicAdd(&g_cnt1[sb.w], 1);
        if (t0 < SLOTS) g_bucket[t0 * NN + sa.x] = da.x;
        if (t1 < SLOTS) g_bucket[t1 * NN + sa.y] = da.y;
        if (t2 < SLOTS) g_bucket[t2 * NN + sa.z] = da.z;
        if (t3 < SLOTS) g_bucket[t3 * NN + sa.w] = da.w;
        if (t4 < SLOTS) g_bucket[t4 * NN + sb.x] = db.x;
        if (t5 < SLOTS) g_bucket[t5 * NN + sb.y] = db.y;
        if (t6 < SLOTS) g_bucket[t6 * NN + sb.z] = db.z;
        if (t7 < SLOTS) g_bucket[t7 * NN + sb.w] = db.w;
    }
    if (j8 == 0) {  // tail (e % 8)
        for (int j = e8 << 3; j < e; j++) {
            int s = src[j];
            int slot = atomicAdd(&g_cnt1[s], 1);
            if (slot < SLOTS) g_bucket[slot * NN + s] = dst[j];
        }
    }
}

// (3) dis = rsqrt(deg+1); fp16 gather table yh = dis * x (24B used per 32B row;
//     halves 12..15 are never read and stay at their zero initialization)
__global__ void k_disy(int n) {
    int i = blockIdx.x * blockDim.x + threadIdx.x;
    if (i < n) {
        float dis = rsqrtf((float)(g_cnt1[i] + 1));
        g_dis[i] = dis;
        const float4* xr = (const float4*)&g_x16[i * 16];
        float4 x0 = xr[0], x1 = xr[1], x2 = xr[2];
        __half2* yr = (__half2*)&g_yh[i * 16];
        yr[0] = __floats2half2_rn(dis * x0.x, dis * x0.y);
        yr[1] = __floats2half2_rn(dis * x0.z, dis * x0.w);
        yr[2] = __floats2half2_rn(dis * x1.x, dis * x1.y);
        yr[3] = __floats2half2_rn(dis * x1.z, dis * x1.w);
        yr[4] = __floats2half2_rn(dis * x2.x, dis * x2.y);
        yr[5] = __floats2half2_rn(dis * x2.z, 0.f);
    }
}

// accumulate one fp16 row (24B: uint4 + uint2) into a[12]
__device__ __forceinline__ void acc_row(const __half* row, float* a) {
    uint4 q0 = *(const uint4*)row;            // halves 0..7
    uint2 q1 = *(const uint2*)(row + 8);      // halves 8..11
    float2 f;
    f = __half22float2(*(const __half2*)&q0.x); a[0] += f.x; a[1] += f.y;
    f = __half22float2(*(const __half2*)&q0.y); a[2] += f.x; a[3] += f.y;
    f = __half22float2(*(const __half2*)&q0.z); a[4] += f.x; a[5] += f.y;
    f = __half22float2(*(const __half2*)&q0.w); a[6] += f.x; a[7] += f.y;
    f = __half22float2(*(const __half2*)&q1.x); a[8] += f.x; a[9] += f.y;
    f = __half22float2(*(const __half2*)&q1.y); a[10] += f.x; a[11] += f.y;
}

// (4) FUSED: gather-aggregate (fp16 table, coalesced bucket) + layer-1 MLP +
//     layer-2 projection + readout sums. ONE thread per node — the verified
//     optimal structure (r8 = 36.7us; 2-thr/node and 4-deep ILP both lost).
__global__ void k_gnode(const float* __restrict__ W1, const float* __restrict__ b1,
                        const float* __restrict__ W2,
                        const float* __restrict__ Wv, const float* __restrict__ Wd,
                        int n) {
    __shared__ float4 sW1[64 * 3];   // W1 transposed per output j (11 used + pad)
    __shared__ float sB1[64], sW2[64], sWv[64], sWd[64], sW2x[12];
    int tid = threadIdx.x;

    for (int idx = tid; idx < 704; idx += blockDim.x) {
        int d = idx >> 6, j = idx & 63;          // W1[d*64 + j]
        ((float*)sW1)[j * 12 + d] = W1[idx];
    }
    for (int j = tid; j < 64; j += blockDim.x) {
        ((float*)sW1)[j * 12 + 11] = 0.f;
        sB1[j] = b1[j];
        sW2[j] = W2[j];
        sWv[j] = Wv[j];
        sWd[j] = Wd[j];
    }
    if (tid < 11) sW2x[tid] = W2[64 + tid];
    __syncthreads();

    int i = blockIdx.x * blockDim.x + tid;
    float pv = 0.f, pd = 0.f;

    if (i < n) {
        int deg = g_cnt1[i];
        int dd = deg < SLOTS ? deg : SLOTS;

        float a[12];
#pragma unroll
        for (int q = 0; q < 12; q++) a[q] = 0.f;

        int k = 0;
        for (; k + 2 <= dd; k += 2) {
            int d0 = g_bucket[k * NN + i];         // coalesced across lanes
            int d1 = g_bucket[(k + 1) * NN + i];
            acc_row(&g_yh[d0 * 16], a);
            acc_row(&g_yh[d1 * 16], a);
        }
        if (k < dd) {
            int d0 = g_bucket[k * NN + i];
            acc_row(&g_yh[d0 * 16], a);
        }

        float di = g_dis[i];
        float di2 = di * di;
        const float4* xr = (const float4*)&g_x16[i * 16];
        float4 x0 = xr[0], x1 = xr[1], x2 = xr[2];

        // self term in exact float: z = di*agg + di^2*x
        float z[12];
        z[0]  = fmaf(di, a[0],  di2 * x0.x);
        z[1]  = fmaf(di, a[1],  di2 * x0.y);
        z[2]  = fmaf(di, a[2],  di2 * x0.z);
        z[3]  = fmaf(di, a[3],  di2 * x0.w);
        z[4]  = fmaf(di, a[4],  di2 * x1.x);
        z[5]  = fmaf(di, a[5],  di2 * x1.y);
        z[6]  = fmaf(di, a[6],  di2 * x1.z);
        z[7]  = fmaf(di, a[7],  di2 * x1.w);
        z[8]  = fmaf(di, a[8],  di2 * x2.x);
        z[9]  = fmaf(di, a[9],  di2 * x2.y);
        z[10] = fmaf(di, a[10], di2 * x2.z);
        z[11] = 0.f;

        float p2 = 0.f;
#pragma unroll 4
        for (int j = 0; j < 64; j++) {
            float4 w0 = sW1[j * 3], w1 = sW1[j * 3 + 1], w2 = sW1[j * 3 + 2];
            float acc = sB1[j];
            acc = fmaf(z[0], w0.x, acc);
            acc = fmaf(z[1], w0.y, acc);
            acc = fmaf(z[2], w0.z, acc);
            acc = fmaf(z[3], w0.w, acc);
            acc = fmaf(z[4], w1.x, acc);
            acc = fmaf(z[5], w1.y, acc);
            acc = fmaf(z[6], w1.z, acc);
            acc = fmaf(z[7], w1.w, acc);
            acc = fmaf(z[8], w2.x, acc);
            acc = fmaf(z[9], w2.y, acc);
            acc = fmaf(z[10], w2.z, acc);
            float h = fmaxf(acc, 0.f);
            p2 = fmaf(h, sW2[j], p2);
            pv = fmaf(h, sWv[j], pv);
            pd = fmaf(h, sWd[j], pd);
        }

        float xa = 0.f;
        xa = fmaf(x0.x, sW2x[0], xa);
        xa = fmaf(x0.y, sW2x[1], xa);
        xa = fmaf(x0.z, sW2x[2], xa);
        xa = fmaf(x0.w, sW2x[3], xa);
        xa = fmaf(x1.x, sW2x[4], xa);
        xa = fmaf(x1.y, sW2x[5], xa);
        xa = fmaf(x1.z, sW2x[6], xa);
        xa = fmaf(x1.w, sW2x[7], xa);
        xa = fmaf(x2.x, sW2x[8], xa);
        xa = fmaf(x2.y, sW2x[9], xa);
        xa = fmaf(x2.z, sW2x[10], xa);
        g_hd[i] = di * (p2 + xa);
    }

    // warp-reduce the readout sums, one atomic pair per warp
#pragma unroll
    for (int off = 16; off; off >>= 1) {
        pv += __shfl_xor_sync(0xffffffffu, pv, off);
        pd += __shfl_xor_sync(0xffffffffu, pd, off);
    }
    if ((tid & 31) == 0) {
        atomicAdd(&g_vd[0], pv);
        atomicAdd(&g_vd[1], pd);
    }
}

// (5) layer-2 aggregation: warp per ready node, straight from the CSR bucket.
__global__ void k_edge2(const int* __restrict__ ridx, int kk) {
    int w = (blockIdx.x * blockDim.x + threadIdx.x) >> 5;
    int lane = threadIdx.x & 31;
    if (w >= kk) return;
    int r = ridx[w];
    int deg = g_cnt1[r];
    int dd = deg < SLOTS ? deg : SLOTS;
    float s = 0.f;
    for (int k = lane; k < dd; k += 32)
        s += g_hd[g_bucket[k * NN + r]];
#pragma unroll
    for (int off = 16; off; off >>= 1)
        s += __shfl_xor_sync(0xffffffffu, s, off);
    if (lane == 0) g_agg2[r] = s;
}

// (6) readout: v, prob_nothing, logits at ready_idx, softmax. One block.
__global__ void k_final(const int* __restrict__ ridx,
                        const float* __restrict__ b2,
                        const float* __restrict__ bd, const float* __restrict__ bv,
                        int k, int n, float* __restrict__ out) {
    __shared__ float s_log[KK + 1];
    __shared__ float s_red[1024];
    __shared__ float s_v, s_pn;
    int t = threadIdx.x;

    if (t == 0) {
        float inv_n = 1.0f / (float)n;
        s_v = g_vd[0] * inv_n + bv[0];
        s_pn = g_vd[1] * inv_n + bd[0];
    }
    __syncthreads();

    float bb2 = b2[0];
    for (int i = t; i <= k; i += blockDim.x) {
        float l;
        if (i < k) {
            int r = ridx[i];
            l = g_dis[r] * (g_agg2[r] + g_hd[r]) + bb2;
        } else {
            l = s_pn;
        }
        s_log[i] = l;
    }
    __syncthreads();

    float m = -1e30f;
    for (int i = t; i <= k; i += blockDim.x) m = fmaxf(m, s_log[i]);
    s_red[t] = m;
    __syncthreads();
    for (int s = 512; s; s >>= 1) {
        if (t < s) s_red[t] = fmaxf(s_red[t], s_red[t + s]);
        __syncthreads();
    }
    float mx = s_red[0];
    __syncthreads();

    float sum = 0.f;
    for (int i = t; i <= k; i += blockDim.x) sum += expf(s_log[i] - mx);
    s_red[t] = sum;
    __syncthreads();
    for (int s = 512; s; s >>= 1) {
        if (t < s) s_red[t] += s_red[t + s];
        __syncthreads();
    }
    float inv = 1.0f / s_red[0];

    for (int i = t; i <= k; i += blockDim.x)
        out[i] = expf(s_log[i] - mx) * inv;
    if (t == 0) out[k + 1] = s_v;
}

// ---------------- launch -----------------------------------------------------

extern "C" void kernel_launch(void* const* d_in, const int* in_sizes, int n_in,
                              void* d_out, int out_size) {
    const float* x   = (const float*)d_in[0];
    const int*   ei  = (const int*)d_in[1];
    const int*   rid = (const int*)d_in[2];
    const float* W1  = (const float*)d_in[3];
    const float* b1  = (const float*)d_in[4];
    const float* W2  = (const float*)d_in[5];
    const float* b2  = (const float*)d_in[6];
    const float* Wd  = (const float*)d_in[7];
    const float* bd  = (const float*)d_in[8];
    const float* Wv  = (const float*)d_in[9];
    const float* bv  = (const float*)d_in[10];

    int n = in_sizes[0] / 11;
    int e = in_sizes[1] / 2;
    int k = in_sizes[2];
    if (n > NN) n = NN;
    if (e > EE) e = EE;
    if (k > KK) k = KK;

    const int* src = ei;
    const int* dst = ei + e;
    int e8 = e >> 3;

    k_init<<<(n + 255) / 256, 256>>>(x, n);             // 1
    k_scatter<<<(e8 + 255) / 256, 256>>>(src, dst, e);  // 2  (8 edges/thread)
    k_disy<<<(n + 255) / 256, 256>>>(n);                // 3
    k_gnode<<<(n + 127) / 128, 128>>>(W1, b1, W2, Wv, Wd, n); // 4  <-- profiled
    k_edge2<<<(k * 32 + 255) / 256, 256>>>(rid, k);     // 5
    k_final<<<1, 1024>>>(rid, b2, bd, bv, k, n, (float*)d_out); // 6
}

// round 15
// speedup vs baseline: 1.0266x; 1.0266x over previous
#include <cuda_runtime.h>
#include <cuda_fp16.h>
#include <math.h>

// Problem constants (fixed by the dataset)
#define NN 100000
#define EE 3200000
#define KK 1024
#define SLOTS 96           // max degree capacity (deg ~ Binom(3.2M,1e-5); deg>=96 is ~11 sigma)

// ---------------- scratch (device globals; no allocation allowed) -----------
__device__ __align__(16) float  g_x16[NN * 16];  // x padded to 64B rows (float, exact)
__device__ __align__(16) __half g_yh[NN * 16];   // dis[i]*x in fp16, 32B rows (12 used + 4 pad)
__device__ int   g_cnt1[NN];           // degree counter / CSR slot allocator
__device__ float g_dis[NN];
__device__ float g_hd[NN];             // dis[i] * (x_input[i] @ W2)
__device__ float g_agg2[NN];           // layer-2 sums (written at ready rows by k_edge2)
__device__ float g_vd[2];              // global sums of h1.Wv and h1.Wd
__device__ int   g_bucket[SLOTS * NN]; // TRANSPOSED CSR: bucket[slot*NN + node] = dst

// ---------------- kernels ---------------------------------------------------

// (1) tiny init: zero degree counters + readout accumulators ONLY.
__global__ void k_init(int n) {
    int i = blockIdx.x * blockDim.x + threadIdx.x;
    if (i < n) g_cnt1[i] = 0;
    if (i < 2) g_vd[i] = 0.f;
}

// (2) one atomic + one store per edge: degree count + transposed CSR fill.
//     4 edges/thread (verified best: 25K warps; 8/thread regressed in r14).
//     At the measured ~150G random-L2-op/s LTS ceiling; 2 ops/edge is the floor.
__device__ __forceinline__ void scat(int s, int d) {
    int slot = atomicAdd(&g_cnt1[s], 1);
    if (slot < SLOTS) g_bucket[slot * NN + s] = d;
}

__global__ void k_scatter(const int* __restrict__ src, const int* __restrict__ dst, int e) {
    int j4 = blockIdx.x * blockDim.x + threadIdx.x;
    int e4 = e >> 2;
    if (j4 < e4) {
        int4 s = ((const int4*)src)[j4];
        int4 d = ((const int4*)dst)[j4];
        scat(s.x, d.x);
        scat(s.y, d.y);
        scat(s.z, d.z);
        scat(s.w, d.w);
    }
    if (j4 == 0) {  // tail (e % 4)
        for (int j = e4 << 2; j < e; j++) scat(src[j], dst[j]);
    }
}

// (3) FUSED table build: reads raw x (scalar loads; rows are only 4B-aligned),
//     writes dis = rsqrt(deg+1), exact float x16 row, and fp16 yh = dis*x row.
//     (x16 construction moved here from k_init: one fewer full sweep over x.)
__global__ void k_disy(const float* __restrict__ x, int n) {
    int i = blockIdx.x * blockDim.x + threadIdx.x;
    if (i < n) {
        float dis = rsqrtf((float)(g_cnt1[i] + 1));
        g_dis[i] = dis;
        const float* p = x + i * 11;
        float v0 = p[0], v1 = p[1], v2 = p[2], v3 = p[3];
        float v4 = p[4], v5 = p[5], v6 = p[6], v7 = p[7];
        float v8 = p[8], v9 = p[9], v10 = p[10];
        float4* o = (float4*)&g_x16[i * 16];
        o[0] = make_float4(v0, v1, v2, v3);
        o[1] = make_float4(v4, v5, v6, v7);
        o[2] = make_float4(v8, v9, v10, 0.f);
        __half2* yr = (__half2*)&g_yh[i * 16];
        yr[0] = __floats2half2_rn(dis * v0, dis * v1);
        yr[1] = __floats2half2_rn(dis * v2, dis * v3);
        yr[2] = __floats2half2_rn(dis * v4, dis * v5);
        yr[3] = __floats2half2_rn(dis * v6, dis * v7);
        yr[4] = __floats2half2_rn(dis * v8, dis * v9);
        yr[5] = __floats2half2_rn(dis * v10, 0.f);
    }
}

// accumulate one fp16 row (24B: uint4 + uint2) into a[12]
__device__ __forceinline__ void acc_row(const __half* row, float* a) {
    uint4 q0 = *(const uint4*)row;            // halves 0..7
    uint2 q1 = *(const uint2*)(row + 8);      // halves 8..11
    float2 f;
    f = __half22float2(*(const __half2*)&q0.x); a[0] += f.x; a[1] += f.y;
    f = __half22float2(*(const __half2*)&q0.y); a[2] += f.x; a[3] += f.y;
    f = __half22float2(*(const __half2*)&q0.z); a[4] += f.x; a[5] += f.y;
    f = __half22float2(*(const __half2*)&q0.w); a[6] += f.x; a[7] += f.y;
    f = __half22float2(*(const __half2*)&q1.x); a[8] += f.x; a[9] += f.y;
    f = __half22float2(*(const __half2*)&q1.y); a[10] += f.x; a[11] += f.y;
}

// (4) FUSED: gather-aggregate (fp16 table, coalesced bucket) + layer-1 MLP +
//     layer-2 projection + readout sums. ONE thread per node, 2-deep gather —
//     the verified-optimal structure (36.5-36.7us across r8/r14; all structural
//     variants in r9/r10/r13 lost).
__global__ void k_gnode(const float* __restrict__ W1, const float* __restrict__ b1,
                        const float* __restrict__ W2,
                        const float* __restrict__ Wv, const float* __restrict__ Wd,
                        int n) {
    __shared__ float4 sW1[64 * 3];   // W1 transposed per output j (11 used + pad)
    __shared__ float sB1[64], sW2[64], sWv[64], sWd[64], sW2x[12];
    int tid = threadIdx.x;

    for (int idx = tid; idx < 704; idx += blockDim.x) {
        int d = idx >> 6, j = idx & 63;          // W1[d*64 + j]
        ((float*)sW1)[j * 12 + d] = W1[idx];
    }
    for (int j = tid; j < 64; j += blockDim.x) {
        ((float*)sW1)[j * 12 + 11] = 0.f;
        sB1[j] = b1[j];
        sW2[j] = W2[j];
        sWv[j] = Wv[j];
        sWd[j] = Wd[j];
    }
    if (tid < 11) sW2x[tid] = W2[64 + tid];
    __syncthreads();

    int i = blockIdx.x * blockDim.x + tid;
    float pv = 0.f, pd = 0.f;

    if (i < n) {
        int deg = g_cnt1[i];
        int dd = deg < SLOTS ? deg : SLOTS;

        float a[12];
#pragma unroll
        for (int q = 0; q < 12; q++) a[q] = 0.f;

        int k = 0;
        for (; k + 2 <= dd; k += 2) {
            int d0 = g_bucket[k * NN + i];         // coalesced across lanes
            int d1 = g_bucket[(k + 1) * NN + i];
            acc_row(&g_yh[d0 * 16], a);
            acc_row(&g_yh[d1 * 16], a);
        }
        if (k < dd) {
            int d0 = g_bucket[k * NN + i];
            acc_row(&g_yh[d0 * 16], a);
        }

        float di = g_dis[i];
        float di2 = di * di;
        const float4* xr = (const float4*)&g_x16[i * 16];
        float4 x0 = xr[0], x1 = xr[1], x2 = xr[2];

        // self term in exact float: z = di*agg + di^2*x
        float z[12];
        z[0]  = fmaf(di, a[0],  di2 * x0.x);
        z[1]  = fmaf(di, a[1],  di2 * x0.y);
        z[2]  = fmaf(di, a[2],  di2 * x0.z);
        z[3]  = fmaf(di, a[3],  di2 * x0.w);
        z[4]  = fmaf(di, a[4],  di2 * x1.x);
        z[5]  = fmaf(di, a[5],  di2 * x1.y);
        z[6]  = fmaf(di, a[6],  di2 * x1.z);
        z[7]  = fmaf(di, a[7],  di2 * x1.w);
        z[8]  = fmaf(di, a[8],  di2 * x2.x);
        z[9]  = fmaf(di, a[9],  di2 * x2.y);
        z[10] = fmaf(di, a[10], di2 * x2.z);
        z[11] = 0.f;

        float p2 = 0.f;
#pragma unroll 4
        for (int j = 0; j < 64; j++) {
            float4 w0 = sW1[j * 3], w1 = sW1[j * 3 + 1], w2 = sW1[j * 3 + 2];
            float acc = sB1[j];
            acc = fmaf(z[0], w0.x, acc);
            acc = fmaf(z[1], w0.y, acc);
            acc = fmaf(z[2], w0.z, acc);
            acc = fmaf(z[3], w0.w, acc);
            acc = fmaf(z[4], w1.x, acc);
            acc = fmaf(z[5], w1.y, acc);
            acc = fmaf(z[6], w1.z, acc);
            acc = fmaf(z[7], w1.w, acc);
            acc = fmaf(z[8], w2.x, acc);
            acc = fmaf(z[9], w2.y, acc);
            acc = fmaf(z[10], w2.z, acc);
            float h = fmaxf(acc, 0.f);
            p2 = fmaf(h, sW2[j], p2);
            pv = fmaf(h, sWv[j], pv);
            pd = fmaf(h, sWd[j], pd);
        }

        float xa = 0.f;
        xa = fmaf(x0.x, sW2x[0], xa);
        xa = fmaf(x0.y, sW2x[1], xa);
        xa = fmaf(x0.z, sW2x[2], xa);
        xa = fmaf(x0.w, sW2x[3], xa);
        xa = fmaf(x1.x, sW2x[4], xa);
        xa = fmaf(x1.y, sW2x[5], xa);
        xa = fmaf(x1.z, sW2x[6], xa);
        xa = fmaf(x1.w, sW2x[7], xa);
        xa = fmaf(x2.x, sW2x[8], xa);
        xa = fmaf(x2.y, sW2x[9], xa);
        xa = fmaf(x2.z, sW2x[10], xa);
        g_hd[i] = di * (p2 + xa);
    }

    // warp-reduce the readout sums, one atomic pair per warp
#pragma unroll
    for (int off = 16; off; off >>= 1) {
        pv += __shfl_xor_sync(0xffffffffu, pv, off);
        pd += __shfl_xor_sync(0xffffffffu, pd, off);
    }
    if ((tid & 31) == 0) {
        atomicAdd(&g_vd[0], pv);
        atomicAdd(&g_vd[1], pd);
    }
}

// (5) layer-2 aggregation: warp per ready node, straight from the CSR bucket.
__global__ void k_edge2(const int* __restrict__ ridx, int kk) {
    int w = (blockIdx.x * blockDim.x + threadIdx.x) >> 5;
    int lane = threadIdx.x & 31;
    if (w >= kk) return;
    int r = ridx[w];
    int deg = g_cnt1[r];
    int dd = deg < SLOTS ? deg : SLOTS;
    float s = 0.f;
    for (int k = lane; k < dd; k += 32)
        s += g_hd[g_bucket[k * NN + r]];
#pragma unroll
    for (int off = 16; off; off >>= 1)
        s += __shfl_xor_sync(0xffffffffu, s, off);
    if (lane == 0) g_agg2[r] = s;
}

// (6) readout: v, prob_nothing, logits at ready_idx, softmax. One block.
__global__ void k_final(const int* __restrict__ ridx,
                        const float* __restrict__ b2,
                        const float* __restrict__ bd, const float* __restrict__ bv,
                        int k, int n, float* __restrict__ out) {
    __shared__ float s_log[KK + 1];
    __shared__ float s_red[1024];
    __shared__ float s_v, s_pn;
    int t = threadIdx.x;

    if (t == 0) {
        float inv_n = 1.0f / (float)n;
        s_v = g_vd[0] * inv_n + bv[0];
        s_pn = g_vd[1] * inv_n + bd[0];
    }
    __syncthreads();

    float bb2 = b2[0];
    for (int i = t; i <= k; i += blockDim.x) {
        float l;
        if (i < k) {
            int r = ridx[i];
            l = g_dis[r] * (g_agg2[r] + g_hd[r]) + bb2;
        } else {
            l = s_pn;
        }
        s_log[i] = l;
    }
    __syncthreads();

    float m = -1e30f;
    for (int i = t; i <= k; i += blockDim.x) m = fmaxf(m, s_log[i]);
    s_red[t] = m;
    __syncthreads();
    for (int s = 512; s; s >>= 1) {
        if (t < s) s_red[t] = fmaxf(s_red[t], s_red[t + s]);
        __syncthreads();
    }
    float mx = s_red[0];
    __syncthreads();

    float sum = 0.f;
    for (int i = t; i <= k; i += blockDim.x) sum += expf(s_log[i] - mx);
    s_red[t] = sum;
    __syncthreads();
    for (int s = 512; s; s >>= 1) {
        if (t < s) s_red[t] += s_red[t + s];
        __syncthreads();
    }
    float inv = 1.0f / s_red[0];

    for (int i = t; i <= k; i += blockDim.x)
        out[i] = expf(s_log[i] - mx) * inv;
    if (t == 0) out[k + 1] = s_v;
}

// ---------------- launch -----------------------------------------------------

extern "C" void kernel_launch(void* const* d_in, const int* in_sizes, int n_in,
                              void* d_out, int out_size) {
    const float* x   = (const float*)d_in[0];
    const int*   ei  = (const int*)d_in[1];
    const int*   rid = (const int*)d_in[2];
    const float* W1  = (const float*)d_in[3];
    const float* b1  = (const float*)d_in[4];
    const float* W2  = (const float*)d_in[5];
    const float* b2  = (const float*)d_in[6];
    const float* Wd  = (const float*)d_in[7];
    const float* bd  = (const float*)d_in[8];
    const float* Wv  = (const float*)d_in[9];
    const float* bv  = (const float*)d_in[10];

    int n = in_sizes[0] / 11;
    int e = in_sizes[1] / 2;
    int k = in_sizes[2];
    if (n > NN) n = NN;
    if (e > EE) e = EE;
    if (k > KK) k = KK;

    const int* src = ei;
    const int* dst = ei + e;
    int e4 = e >> 2;

    k_init<<<(n + 255) / 256, 256>>>(n);                 // 1  (counters only)
    k_scatter<<<(e4 + 255) / 256, 256>>>(src, dst, e);   // 2  (4 edges/thread, verified best)
    k_disy<<<(n + 255) / 256, 256>>>(x, n);              // 3  (x16 + yh + dis in one pass)
    k_gnode<<<(n + 127) / 128, 128>>>(W1, b1, W2, Wv, Wd, n); // 4  <-- profiled
    k_edge2<<<(k * 32 + 255) / 256, 256>>>(rid, k);      // 5
    k_final<<<1, 1024>>>(rid, b2, bd, bv, k, n, (float*)d_out); // 6
}